// round 12
// baseline (speedup 1.0000x reference)
#include <cuda_runtime.h>

#define Bn  4
#define Cn  128
#define Ln  16
#define Kn  64
#define CDn 8
#define HW  4096

typedef unsigned int u32;

// ---- helpers ----
__device__ __forceinline__ u32 tf32_rna(float x) {
    u32 r; asm("cvt.rna.tf32.f32 %0, %1;" : "=r"(r) : "f"(x)); return r;
}
__device__ __forceinline__ void tfsplit(float v, float& hi, float& lo) {
    const u32 h = tf32_rna(v);
    hi = __uint_as_float(h);
    lo = __uint_as_float(tf32_rna(v - hi));
}
// m16n8k8 tf32 MMA: D(16x8) += A(16x8,row) * B(8x8,col); fp32 accum.
__device__ __forceinline__ void mma8(float& d0, float& d1, float& d2, float& d3,
                                     u32 a0, u32 a1, u32 a2, u32 a3,
                                     u32 b0, u32 b1) {
    asm volatile(
        "mma.sync.aligned.m16n8k8.row.col.f32.tf32.tf32.f32 "
        "{%0,%1,%2,%3}, {%4,%5,%6,%7}, {%8,%9}, {%0,%1,%2,%3};"
        : "+f"(d0), "+f"(d1), "+f"(d2), "+f"(d3)
        : "r"(a0), "r"(a1), "r"(a2), "r"(a3), "r"(b0), "r"(b1));
}

#define ZSTR 264   // px stride for z smem: (264*j+p)%32 == (8j+p)%32 -> conflict-free frags
#define CSTR 72    // code stride for code smem: (72*j+n)%32 == (8j+n)%32

// One CTA: one latent slot l, 256 consecutive pixels of one batch plane.
// scores(256x64) = Z(256x8) @ C(64x8)^T - 0.5|c|^2 via 3xTF32 mma.sync
// (exact fp32 bias in accumulator). Per-row argmax via mantissa-tagged
// FMNMX top-2 + quad butterfly; TAU-guarded exact scalar fallback.
__global__ __launch_bounds__(256) void vq_mma_kernel(
    const float* __restrict__ z,      // (B, C, H, W)
    const float* __restrict__ codes,  // (L, K, CD)
    float* __restrict__ qout,
    float* __restrict__ idxf,
    int*   __restrict__ idxi)
{
    __shared__ float zh[CDn][ZSTR], zl[CDn][ZSTR];   // 16.9 KB
    __shared__ float ch[CDn][CSTR], cl[CDn][CSTR];   // 4.6 KB
    __shared__ float bias[Kn];
    __shared__ float cpos[Kn * CDn];                  // exact codes (gather/output)
    __shared__ u32   kbst[256];

    const int tid  = threadIdx.x;
    const int warp = tid >> 5;
    const int lane = tid & 31;
    const int g    = lane >> 2;       // group id (row within fragment)
    const int tg   = lane & 3;        // thread-in-group (k / col pairs)
    const int l    = blockIdx.x;
    const int b    = blockIdx.z;
    const int hw0  = blockIdx.y * 256;

    // ---- Codes: 64 codes, one per thread (tid<64) ----
    if (tid < Kn) {
        const float4 va = reinterpret_cast<const float4*>(codes + (l * Kn + tid) * CDn)[0];
        const float4 vb = reinterpret_cast<const float4*>(codes + (l * Kn + tid) * CDn)[1];
        float cs[8] = {va.x, va.y, va.z, va.w, vb.x, vb.y, vb.z, vb.w};
        float hs = 0.f;
        #pragma unroll
        for (int j = 0; j < CDn; j++) hs = fmaf(cs[j], cs[j], hs);
        bias[tid] = -0.5f * hs;
        #pragma unroll
        for (int j = 0; j < CDn; j++) {
            float hi, lo; tfsplit(cs[j], hi, lo);
            ch[j][tid] = hi;
            cl[j][tid] = lo;
            cpos[tid * CDn + j] = cs[j];
        }
    }

    // ---- Z: 256 px x 8 dims, coalesced; split hi/lo into smem ----
    #pragma unroll
    for (int j = 0; j < CDn; j++) {
        const float v = z[(b * Cn + l * CDn + j) * HW + hw0 + tid];
        float hi, lo; tfsplit(v, hi, lo);
        zh[j][tid] = hi;
        zl[j][tid] = lo;
    }
    __syncthreads();

    // ---- A fragments for 2 m-tiles (32 px per warp) ----
    const int pxb = warp * 32;
    u32 ah[2][4], al[2][4];
    #pragma unroll
    for (int m = 0; m < 2; m++) {
        const int p0 = pxb + m * 16 + g;
        ah[m][0] = __float_as_uint(zh[tg    ][p0    ]);
        ah[m][1] = __float_as_uint(zh[tg    ][p0 + 8]);
        ah[m][2] = __float_as_uint(zh[tg + 4][p0    ]);
        ah[m][3] = __float_as_uint(zh[tg + 4][p0 + 8]);
        al[m][0] = __float_as_uint(zl[tg    ][p0    ]);
        al[m][1] = __float_as_uint(zl[tg    ][p0 + 8]);
        al[m][2] = __float_as_uint(zl[tg + 4][p0    ]);
        al[m][3] = __float_as_uint(zl[tg + 4][p0 + 8]);
    }

    // ---- Main loop: 8 n-tiles of 8 codes ----
    float m1[2][2] = {{-3.4e38f, -3.4e38f}, {-3.4e38f, -3.4e38f}};
    float m2[2][2] = {{-3.4e38f, -3.4e38f}, {-3.4e38f, -3.4e38f}};

    #pragma unroll
    for (int nt = 0; nt < 8; nt++) {
        const int nb = nt * 8;
        const u32 bh0 = __float_as_uint(ch[tg    ][nb + g]);
        const u32 bh1 = __float_as_uint(ch[tg + 4][nb + g]);
        const u32 bl0 = __float_as_uint(cl[tg    ][nb + g]);
        const u32 bl1 = __float_as_uint(cl[tg + 4][nb + g]);
        const float bs0 = bias[nb + 2 * tg];
        const float bs1 = bias[nb + 2 * tg + 1];
        const u32 t0 = (u32)(63 - (nb + 2 * tg));   // tag for col0
        const u32 t1 = t0 - 1u;                      // tag for col0+1
        #pragma unroll
        for (int m = 0; m < 2; m++) {
            float d0 = bs0, d1 = bs1, d2 = bs0, d3 = bs1;
            mma8(d0, d1, d2, d3, ah[m][0], ah[m][1], ah[m][2], ah[m][3], bh0, bh1);
            mma8(d0, d1, d2, d3, ah[m][0], ah[m][1], ah[m][2], ah[m][3], bl0, bl1);
            mma8(d0, d1, d2, d3, al[m][0], al[m][1], al[m][2], al[m][3], bh0, bh1);
            // mantissa-tagged top-2 tracking (rows g -> [m][0], g+8 -> [m][1])
            const float p0 = __uint_as_float((__float_as_uint(d0) & 0xFFFFFFC0u) | t0);
            const float p1 = __uint_as_float((__float_as_uint(d1) & 0xFFFFFFC0u) | t1);
            const float p2 = __uint_as_float((__float_as_uint(d2) & 0xFFFFFFC0u) | t0);
            const float p3 = __uint_as_float((__float_as_uint(d3) & 0xFFFFFFC0u) | t1);
            float o;
            o = m1[m][0]; m1[m][0] = fmaxf(o, p0); m2[m][0] = fmaxf(m2[m][0], fminf(o, p0));
            o = m1[m][0]; m1[m][0] = fmaxf(o, p1); m2[m][0] = fmaxf(m2[m][0], fminf(o, p1));
            o = m1[m][1]; m1[m][1] = fmaxf(o, p2); m2[m][1] = fmaxf(m2[m][1], fminf(o, p2));
            o = m1[m][1]; m1[m][1] = fmaxf(o, p3); m2[m][1] = fmaxf(m2[m][1], fminf(o, p3));
        }
    }

    // ---- Quad butterfly reduce (lanes xor 1, xor 2 share the same rows) ----
    #pragma unroll
    for (int s = 1; s <= 2; s <<= 1) {
        #pragma unroll
        for (int m = 0; m < 2; m++) {
            #pragma unroll
            for (int r = 0; r < 2; r++) {
                const float om1 = __shfl_xor_sync(0xffffffffu, m1[m][r], s);
                const float om2 = __shfl_xor_sync(0xffffffffu, m2[m][r], s);
                m2[m][r] = fmaxf(fmaxf(m2[m][r], om2), fminf(m1[m][r], om1));
                m1[m][r] = fmaxf(m1[m][r], om1);
            }
        }
    }

    // ---- Stage winner + guard flag (lane tg==0 of each quad) ----
    if (tg == 0) {
        #pragma unroll
        for (int m = 0; m < 2; m++) {
            #pragma unroll
            for (int r = 0; r < 2; r++) {
                const float v1 = m1[m][r], v2 = m2[m][r];
                const int kb = 63 - (int)(__float_as_uint(v1) & 63u);
                const float tau = 2e-4f + 2e-5f * fabsf(v1);
                const u32 st = (u32)kb | (((v1 - v2) < tau) ? 256u : 0u);
                kbst[pxb + m * 16 + r * 8 + g] = st;
            }
        }
    }
    __syncthreads();

    // ---- Output phase: thread t handles pixel t (fully coalesced) ----
    const u32 st = kbst[tid];
    int kb = (int)(st & 63u);

    if (__any_sync(0xffffffffu, st & 256u)) {
        if (st & 256u) {
            // exact diff-form argmin (strict <, first-k-wins) — rare
            float z8[8];
            #pragma unroll
            for (int j = 0; j < CDn; j++)
                z8[j] = z[(b * Cn + l * CDn + j) * HW + hw0 + tid];
            float best = 3.4e38f;
            int bi = 0;
            #pragma unroll 1
            for (int k = 0; k < Kn; k++) {
                const float* cp = cpos + k * CDn;
                float d = 0.f;
                #pragma unroll
                for (int j = 0; j < CDn; j++) {
                    const float t = z8[j] - cp[j];
                    d = fmaf(t, t, d);
                }
                if (d < best) { best = d; bi = k; }
            }
            kb = bi;
        }
    }

    const float* cp = cpos + kb * CDn;
    if (qout) {
        float* qb = qout + (b * Cn + l * CDn) * HW + hw0 + tid;
        #pragma unroll
        for (int j = 0; j < CDn; j++) qb[j * HW] = cp[j];
    }
    const long long io = ((long long)(b * HW + hw0 + tid)) * Ln + l;
    if (idxf) idxf[io] = (float)kb;
    if (idxi) idxi[io] = kb;
}

extern "C" void kernel_launch(void* const* d_in, const int* in_sizes, int n_in,
                              void* d_out, int out_size)
{
    const float* z     = (const float*)d_in[0];
    const float* codes = (const float*)d_in[1];
    if (n_in >= 2 && in_sizes[0] == Ln * Kn * CDn && in_sizes[1] == Bn * Cn * HW) {
        codes = (const float*)d_in[0];
        z     = (const float*)d_in[1];
    }

    const int NQ = Bn * Cn * HW;       // 2097152
    const int NI = Bn * HW * Ln;       // 262144

    float* qout = nullptr;
    float* idxf = nullptr;
    int*   idxi = nullptr;

    if (out_size >= NQ + NI) {
        qout = (float*)d_out;
        idxf = (float*)d_out + NQ;
    } else if (out_size == NI) {
        idxi = (int*)d_out;
    } else {
        qout = (float*)d_out;
    }

    dim3 grid(Ln, HW / 256, Bn);   // (16, 16, 4) = 1024 CTAs
    dim3 block(256, 1, 1);
    vq_mma_kernel<<<grid, block>>>(z, codes, qout, idxf, idxi);
}